// round 1
// baseline (speedup 1.0000x reference)
#include <cuda_runtime.h>
#include <cuda_bf16.h>

// Problem constants
#define BB   4
#define HH   160
#define WW   288
#define HO   80
#define WO   144
#define HWO  (HO*WO)     // 11520
#define DMAX 24
#define EPSV 1e-5f

// Scratch (no allocation allowed -> __device__ globals)
__device__ float d_gy[BB*192*HWO];   // gwc conv1+bn+lrelu output (4,192,80,144)
__device__ float d_cy[BB*24*HWO];    // cat conv1+bn+lrelu output (4,24,80,144)
__device__ float d_g8[BB*96*HWO];    // gwc downsampled features  (4,96,80,144)
__device__ float d_c8[BB*12*HWO];    // cat downsampled features  (4,12,80,144)

// ---------------------------------------------------------------------------
// Kernel 1: 3x3 stride-2 pad-1 conv + BN + LeakyReLU(0.1)
// Tile: 8x16 output pixels, 32 output channels per block, ic chunks of 4.
// ---------------------------------------------------------------------------
template<int CIN, int COUT>
__global__ __launch_bounds__(256)
void conv1_bn_lrelu(const float* __restrict__ x, const float* __restrict__ w,
                    const float* __restrict__ bng, const float* __restrict__ bnb,
                    const float* __restrict__ bnm, const float* __restrict__ bnv,
                    float* __restrict__ y)
{
    constexpr int NOC = (COUT + 31) / 32;
    const int bz      = blockIdx.z;
    const int b       = bz / NOC;
    const int oc_base = (bz % NOC) * 32;
    const int oh0 = blockIdx.y * 8;
    const int ow0 = blockIdx.x * 16;
    const int ih0 = oh0 * 2 - 1;
    const int iw0 = ow0 * 2 - 1;

    __shared__ __align__(16) float in_s[4 * 17 * 33];   // 4 ic x 17h x 33w
    __shared__ __align__(16) float w_s[4 * 9 * 32];     // [ic*9+k][oc_local]

    const int tid = threadIdx.x;
    const int oq  = tid >> 5;          // 0..7  -> oc group of 4
    const int pq  = tid & 31;          // 0..31 -> pixel group of 4
    const int ph  = pq >> 2;           // 0..7
    const int pw0 = (pq & 3) * 4;      // 0,4,8,12

    float acc[4][4];
    #pragma unroll
    for (int o = 0; o < 4; ++o)
        #pragma unroll
        for (int j = 0; j < 4; ++j) acc[o][j] = 0.f;

    for (int ic0 = 0; ic0 < CIN; ic0 += 4) {
        // cooperative input patch load (with zero padding)
        for (int idx = tid; idx < 4 * 561; idx += 256) {
            int ic  = idx / 561, rem = idx % 561;
            int ih  = rem / 33, iw = rem % 33;
            int gh  = ih0 + ih, gw = iw0 + iw;
            float v = 0.f;
            if ((unsigned)gh < (unsigned)HH && (unsigned)gw < (unsigned)WW)
                v = x[(((size_t)b * CIN + ic0 + ic) * HH + gh) * WW + gw];
            in_s[idx] = v;
        }
        // cooperative weight load, oc-fastest layout for float4 broadcast
        for (int idx = tid; idx < 1152; idx += 256) {
            int oc_l = idx & 31;
            int r    = idx >> 5;             // ic*9 + k
            int ic   = r / 9, k = r % 9;
            int oc_g = oc_base + oc_l;
            float v  = 0.f;
            if (oc_g < COUT) v = w[((size_t)oc_g * CIN + ic0 + ic) * 9 + k];
            w_s[r * 32 + oc_l] = v;
        }
        __syncthreads();

        #pragma unroll
        for (int ic = 0; ic < 4; ++ic) {
            #pragma unroll
            for (int kh = 0; kh < 3; ++kh) {
                #pragma unroll
                for (int kw = 0; kw < 3; ++kw) {
                    float4 wv = *(const float4*)&w_s[((ic * 9) + kh * 3 + kw) * 32 + oq * 4];
                    const float* ip = &in_s[ic * 561 + (ph * 2 + kh) * 33 + pw0 * 2 + kw];
                    float i0 = ip[0], i1 = ip[2], i2 = ip[4], i3 = ip[6];
                    acc[0][0] += wv.x * i0; acc[0][1] += wv.x * i1; acc[0][2] += wv.x * i2; acc[0][3] += wv.x * i3;
                    acc[1][0] += wv.y * i0; acc[1][1] += wv.y * i1; acc[1][2] += wv.y * i2; acc[1][3] += wv.y * i3;
                    acc[2][0] += wv.z * i0; acc[2][1] += wv.z * i1; acc[2][2] += wv.z * i2; acc[2][3] += wv.z * i3;
                    acc[3][0] += wv.w * i0; acc[3][1] += wv.w * i1; acc[3][2] += wv.w * i2; acc[3][3] += wv.w * i3;
                }
            }
        }
        __syncthreads();
    }

    // BN + LeakyReLU epilogue
    #pragma unroll
    for (int o = 0; o < 4; ++o) {
        int oc_g = oc_base + oq * 4 + o;
        if (oc_g < COUT) {
            float sc = bng[oc_g] * rsqrtf(bnv[oc_g] + EPSV);
            float sh = bnb[oc_g] - bnm[oc_g] * sc;
            #pragma unroll
            for (int j = 0; j < 4; ++j) {
                float v = acc[o][j] * sc + sh;
                v = (v >= 0.f) ? v : 0.1f * v;
                y[(((size_t)b * COUT + oc_g) * HO + oh0 + ph) * WO + ow0 + pw0 + j] = v;
            }
        }
    }
}

// ---------------------------------------------------------------------------
// Kernel 2: fused 1x1 conv (mask logits) + softmax over 9 taps + weighted
// unfold aggregation. One thread = one output pixel; groups iterated with the
// group's 9xYC weight chunk staged in shared (t padded to 12 for float4).
// ---------------------------------------------------------------------------
template<int YC, int NG, int CPG>
__global__ __launch_bounds__(128)
void mask_agg(const float* __restrict__ y, const float* __restrict__ w2,
              const float* __restrict__ x, float* __restrict__ out)
{
    constexpr int XC = NG * CPG;
    const int pix = blockIdx.x * 128 + threadIdx.x;   // exact grid: BB*HWO/128
    const int b   = pix / HWO;
    const int rem = pix % HWO;
    const int oh  = rem / WO, ow = rem % WO;

    __shared__ __align__(16) float w_s[YC * 12];

    const float* yp = y + (size_t)b * YC * HWO + rem;

    for (int g = 0; g < NG; ++g) {
        for (int idx = threadIdx.x; idx < YC * 9; idx += 128) {
            int ic = idx % YC, t = idx / YC;
            w_s[ic * 12 + t] = w2[((size_t)(g * 9 + t)) * YC + ic];
        }
        __syncthreads();

        float acc[9];
        #pragma unroll
        for (int t = 0; t < 9; ++t) acc[t] = 0.f;

        #pragma unroll 4
        for (int ic = 0; ic < YC; ++ic) {
            float yv = yp[(size_t)ic * HWO];
            const float* wp = &w_s[ic * 12];
            float4 wa = *(const float4*)wp;
            float4 wb = *(const float4*)(wp + 4);
            float  wc = wp[8];
            acc[0] += wa.x * yv; acc[1] += wa.y * yv; acc[2] += wa.z * yv;
            acc[3] += wa.w * yv; acc[4] += wb.x * yv; acc[5] += wb.y * yv;
            acc[6] += wb.z * yv; acc[7] += wb.w * yv; acc[8] += wc   * yv;
        }

        // softmax over the 9 taps
        float m = acc[0];
        #pragma unroll
        for (int t = 1; t < 9; ++t) m = fmaxf(m, acc[t]);
        float e[9], s = 0.f;
        #pragma unroll
        for (int t = 0; t < 9; ++t) { e[t] = __expf(acc[t] - m); s += e[t]; }
        float inv = 1.f / s;
        #pragma unroll
        for (int t = 0; t < 9; ++t) e[t] *= inv;

        // weighted aggregation of the unfold patch
        #pragma unroll
        for (int i = 0; i < CPG; ++i) {
            int c = i * NG + g;
            const float* xc = x + ((size_t)(b * XC + c)) * HH * WW;
            float sum = 0.f;
            #pragma unroll
            for (int kh = 0; kh < 3; ++kh) {
                int ih = 2 * oh + kh - 1;
                #pragma unroll
                for (int kw = 0; kw < 3; ++kw) {
                    int iw = 2 * ow + kw - 1;
                    float xv = 0.f;
                    if ((unsigned)ih < (unsigned)HH && (unsigned)iw < (unsigned)WW)
                        xv = xc[ih * WW + iw];
                    sum += e[kh * 3 + kw] * xv;
                }
            }
            out[((size_t)(b * XC + c)) * HWO + rem] = sum;
        }
        __syncthreads();
    }
}

// ---------------------------------------------------------------------------
// Kernel 3: group-wise correlation volume. Block = (h, g, b); a full row of
// l (12x144) and r (12x144) in shared; l cached in registers per thread.
// out[b, g, d, h, w] = mean_c l[g*12+c, h, w] * r[g*12+c, h, w-d]
// ---------------------------------------------------------------------------
__global__ __launch_bounds__(160)
void gwc_vol(const float* __restrict__ g8, float* __restrict__ out)
{
    const int h = blockIdx.x;
    const int g = blockIdx.y;
    const int b = blockIdx.z;

    __shared__ float ls[12][WO];
    __shared__ float rs[12][WO];

    for (int idx = threadIdx.x; idx < 2 * 12 * WO; idx += 160) {
        int half = idx / (12 * WO);
        int rem  = idx % (12 * WO);
        int c = rem / WO, w = rem % WO;
        int bb = half == 0 ? b : b + 2;
        float v = g8[(((size_t)bb * 96 + g * 12 + c) * HO + h) * WO + w];
        if (half == 0) ls[c][w] = v; else rs[c][w] = v;
    }
    __syncthreads();

    const int w = threadIdx.x;
    if (w < WO) {
        float lr[12];
        #pragma unroll
        for (int c = 0; c < 12; ++c) lr[c] = ls[c][w];
        for (int d = 0; d < DMAX; ++d) {
            float s = 0.f;
            if (w >= d) {
                #pragma unroll
                for (int c = 0; c < 12; ++c) s += lr[c] * rs[c][w - d];
                s *= (1.f / 12.f);
            }
            out[((((size_t)b * 32 + g) * DMAX + d) * HO + h) * WO + w] = s;
        }
    }
}

// ---------------------------------------------------------------------------
// Kernel 4: concat volume — pure gather into out channels [8, 32).
// ---------------------------------------------------------------------------
__global__ __launch_bounds__(256)
void cat_vol(const float* __restrict__ c8, float* __restrict__ out)
{
    int idx = blockIdx.x * 256 + threadIdx.x;   // exact: 2*24*24*80*144 / 256
    int w = idx % WO; int t = idx / WO;
    int h = t % HO; t /= HO;
    int d = t % DMAX; t /= DMAX;
    int ch = t % 24; int b = t / 24;

    float v = 0.f;
    if (w >= d) {
        v = (ch < 12)
          ? c8[(((size_t)b * 12 + ch) * HO + h) * WO + w]
          : c8[((((size_t)b + 2) * 12 + (ch - 12)) * HO + h) * WO + (w - d)];
    }
    out[((((size_t)b * 32 + 8 + ch) * DMAX + d) * HO + h) * WO + w] = v;
}

// ---------------------------------------------------------------------------
extern "C" void kernel_launch(void* const* d_in, const int* in_sizes, int n_in,
                              void* d_out, int out_size)
{
    const float* gwc_x   = (const float*)d_in[0];
    const float* cat_x   = (const float*)d_in[1];
    const float* g_w1    = (const float*)d_in[2];
    const float* g_bng   = (const float*)d_in[3];
    const float* g_bnb   = (const float*)d_in[4];
    const float* g_bnm   = (const float*)d_in[5];
    const float* g_bnv   = (const float*)d_in[6];
    const float* g_w2    = (const float*)d_in[7];
    const float* c_w1    = (const float*)d_in[8];
    const float* c_bng   = (const float*)d_in[9];
    const float* c_bnb   = (const float*)d_in[10];
    const float* c_bnm   = (const float*)d_in[11];
    const float* c_bnv   = (const float*)d_in[12];
    const float* c_w2    = (const float*)d_in[13];
    float* out = (float*)d_out;

    float *gy, *cy, *g8, *c8;
    cudaGetSymbolAddress((void**)&gy, d_gy);
    cudaGetSymbolAddress((void**)&cy, d_cy);
    cudaGetSymbolAddress((void**)&g8, d_g8);
    cudaGetSymbolAddress((void**)&c8, d_c8);

    // conv1 + BN + LeakyReLU
    conv1_bn_lrelu<96, 192><<<dim3(WO/16, HO/8, BB * 6), 256>>>(
        gwc_x, g_w1, g_bng, g_bnb, g_bnm, g_bnv, gy);
    conv1_bn_lrelu<12, 24><<<dim3(WO/16, HO/8, BB * 1), 256>>>(
        cat_x, c_w1, c_bng, c_bnb, c_bnm, c_bnv, cy);

    // fused 1x1 conv + softmax + unfold aggregation
    mask_agg<192, 16, 6><<<BB * HWO / 128, 128>>>(gy, g_w2, gwc_x, g8);
    mask_agg<24, 12, 1><<<BB * HWO / 128, 128>>>(cy, c_w2, cat_x, c8);

    // cost volumes
    gwc_vol<<<dim3(HO, 8, 2), 160>>>(g8, out);
    cat_vol<<<(2 * 24 * DMAX * HO * WO) / 256, 256>>>(c8, out);
}